// round 1
// baseline (speedup 1.0000x reference)
#include <cuda_runtime.h>
#include <cstdint>

// Problem constants
// x:  [8, 2048, 1024] fp32
// Wq/Wk/Wv: [1024, 1024] fp32
// out: [8, 2048, 1024] fp32  (causal single-head attention)

#define NSEQ 2048
#define DIN  1024
#define DOUT 1024
#define BATCH 8

// Scratch (allocation-free rule: __device__ globals)
__device__ float g_Q[(size_t)BATCH * NSEQ * DOUT];
__device__ float g_K[(size_t)BATCH * NSEQ * DOUT];
__device__ float g_V[(size_t)BATCH * NSEQ * DOUT];
__device__ float g_S[(size_t)BATCH * NSEQ * NSEQ];

// ---------------------------------------------------------------------------
// 128x128 tile GEMM core, BK=8, 256 threads, 8x8 per thread, float4 I/O.
// NT=false: C[r,c] = sum_k A[r,k] * B[k,c]   (A row-major lda, B row-major ldb)
// NT=true : C[r,c] = sum_k A[r,k] * B[c,k]   (both row-major with K contiguous)
// kEnd must be a multiple of 8. rowBase/colBase are multiples of 128.
// ---------------------------------------------------------------------------
template <bool NT>
__device__ __forceinline__ void gemm128(
    const float* __restrict__ A, int lda,
    const float* __restrict__ B, int ldb,
    float*       __restrict__ C, int ldc,
    int rowBase, int colBase, int kEnd)
{
    __shared__ float As[8][128];
    __shared__ float Bs[8][128];

    const int tid = threadIdx.x;

    // A loader: 128x8 tile, each thread one float4 (transposed store)
    const int aRow = tid >> 1;           // 0..127
    const int aCol = (tid & 1) * 4;      // 0 or 4

    // B loader (NN): 8x128 tile, each thread one float4 (direct store)
    const int bRow = tid >> 5;           // 0..7
    const int bCol = (tid & 31) * 4;     // 0..124

    // thread micro-tile position (16x16 thread grid of 8x8 tiles)
    const int tr = (tid >> 4) * 8;
    const int tc = (tid & 15) * 8;

    float acc[8][8];
#pragma unroll
    for (int i = 0; i < 8; i++)
#pragma unroll
        for (int j = 0; j < 8; j++) acc[i][j] = 0.0f;

    for (int k0 = 0; k0 < kEnd; k0 += 8) {
        // load A tile (transposed into As[k][m])
        float4 av = *(const float4*)&A[(size_t)(rowBase + aRow) * lda + k0 + aCol];
        As[aCol + 0][aRow] = av.x;
        As[aCol + 1][aRow] = av.y;
        As[aCol + 2][aRow] = av.z;
        As[aCol + 3][aRow] = av.w;

        if (NT) {
            // B is [N, K] row-major: load like A, store transposed into Bs[k][n]
            float4 bv = *(const float4*)&B[(size_t)(colBase + aRow) * ldb + k0 + aCol];
            Bs[aCol + 0][aRow] = bv.x;
            Bs[aCol + 1][aRow] = bv.y;
            Bs[aCol + 2][aRow] = bv.z;
            Bs[aCol + 3][aRow] = bv.w;
        } else {
            float4 bv = *(const float4*)&B[(size_t)(k0 + bRow) * ldb + colBase + bCol];
            *(float4*)&Bs[bRow][bCol] = bv;
        }
        __syncthreads();

#pragma unroll
        for (int kk = 0; kk < 8; ++kk) {
            float4 a0 = *(const float4*)&As[kk][tr];
            float4 a1 = *(const float4*)&As[kk][tr + 4];
            float4 b0 = *(const float4*)&Bs[kk][tc];
            float4 b1 = *(const float4*)&Bs[kk][tc + 4];
            float ar[8] = {a0.x, a0.y, a0.z, a0.w, a1.x, a1.y, a1.z, a1.w};
            float br[8] = {b0.x, b0.y, b0.z, b0.w, b1.x, b1.y, b1.z, b1.w};
#pragma unroll
            for (int i = 0; i < 8; i++)
#pragma unroll
                for (int j = 0; j < 8; j++) acc[i][j] = fmaf(ar[i], br[j], acc[i][j]);
        }
        __syncthreads();
    }

#pragma unroll
    for (int i = 0; i < 8; i++) {
#pragma unroll
        for (int j = 0; j < 8; j += 4) {
            *(float4*)&C[(size_t)(rowBase + tr + i) * ldc + colBase + tc + j] =
                make_float4(acc[i][j], acc[i][j + 1], acc[i][j + 2], acc[i][j + 3]);
        }
    }
}

// ---------------------------------------------------------------------------
// Kernel 1: fused QKV projection. blockIdx.z selects Wq/Wk/Wv and output.
// grid: (DOUT/128=8, B*N/128=128, 3)
// ---------------------------------------------------------------------------
__global__ void __launch_bounds__(256) qkv_kernel(
    const float* __restrict__ X,
    const float* __restrict__ Wq,
    const float* __restrict__ Wk,
    const float* __restrict__ Wv)
{
    const float* W = (blockIdx.z == 0) ? Wq : (blockIdx.z == 1) ? Wk : Wv;
    float* out     = (blockIdx.z == 0) ? g_Q : (blockIdx.z == 1) ? g_K : g_V;
    gemm128<false>(X, DIN, W, DOUT, out, DOUT,
                   blockIdx.y * 128, blockIdx.x * 128, DIN);
}

// ---------------------------------------------------------------------------
// Kernel 2: scores S = Q K^T per batch, causal tile skip.
// grid: (16 kTiles, 16 qTiles, 8 batches)
// ---------------------------------------------------------------------------
__global__ void __launch_bounds__(256) score_kernel()
{
    const int b  = blockIdx.z;
    const int qT = blockIdx.y;
    const int kT = blockIdx.x;
    if (kT > qT) return;  // fully masked tile: softmax never reads it

    const float* Qb = g_Q + (size_t)b * NSEQ * DOUT;
    const float* Kb = g_K + (size_t)b * NSEQ * DOUT;
    float*       Sb = g_S + (size_t)b * NSEQ * NSEQ;
    gemm128<true>(Qb, DOUT, Kb, DOUT, Sb, NSEQ,
                  qT * 128, kT * 128, DOUT);
}

// ---------------------------------------------------------------------------
// Kernel 3: causal softmax, one block per row. Scale 1/sqrt(1024) = 1/32.
// Zero-fills masked entries up to the 128-aligned boundary so PV can read
// block-granular K ranges.
// grid: (B*N = 16384), block: 256
// ---------------------------------------------------------------------------
__global__ void __launch_bounds__(256) softmax_kernel()
{
    const int row = blockIdx.x;
    const int b   = row >> 11;          // /2048
    const int q   = row & (NSEQ - 1);
    float* s = g_S + (size_t)b * NSEQ * NSEQ + (size_t)q * NSEQ;

    const int len        = q + 1;
    const int alignedLen = (len + 127) & ~127;

    float v[8];
    float m = -1e30f;
#pragma unroll
    for (int i = 0; i < 8; i++) {
        int idx = threadIdx.x + i * 256;
        v[i] = (idx < len) ? s[idx] * 0.03125f : -1e30f;
        m = fmaxf(m, v[i]);
    }

    __shared__ float red[256];
    red[threadIdx.x] = m;
    __syncthreads();
#pragma unroll
    for (int off = 128; off > 0; off >>= 1) {
        if (threadIdx.x < off)
            red[threadIdx.x] = fmaxf(red[threadIdx.x], red[threadIdx.x + off]);
        __syncthreads();
    }
    m = red[0];
    __syncthreads();

    float sum = 0.0f;
#pragma unroll
    for (int i = 0; i < 8; i++) {
        float e = __expf(v[i] - m);   // masked lanes: exp(-huge) == 0
        v[i] = e;
        sum += e;
    }
    red[threadIdx.x] = sum;
    __syncthreads();
#pragma unroll
    for (int off = 128; off > 0; off >>= 1) {
        if (threadIdx.x < off)
            red[threadIdx.x] += red[threadIdx.x + off];
        __syncthreads();
    }
    const float inv = 1.0f / red[0];

#pragma unroll
    for (int i = 0; i < 8; i++) {
        int idx = threadIdx.x + i * 256;
        if (idx < alignedLen)
            s[idx] = (idx < len) ? v[i] * inv : 0.0f;
    }
}

// ---------------------------------------------------------------------------
// Kernel 4: context = P V per batch, causal K-extent per qTile.
// grid: (DOUT/128=8, 16 qTiles, 8 batches)
// ---------------------------------------------------------------------------
__global__ void __launch_bounds__(256) pv_kernel(float* __restrict__ out)
{
    const int b  = blockIdx.z;
    const int qT = blockIdx.y;
    const float* Sb = g_S + (size_t)b * NSEQ * NSEQ;
    const float* Vb = g_V + (size_t)b * NSEQ * DOUT;
    float*       Ob = out + (size_t)b * NSEQ * DOUT;
    gemm128<false>(Sb, NSEQ, Vb, DOUT, Ob, DOUT,
                   qT * 128, blockIdx.x * 128, (qT + 1) * 128);
}

// ---------------------------------------------------------------------------
extern "C" void kernel_launch(void* const* d_in, const int* in_sizes, int n_in,
                              void* d_out, int out_size)
{
    (void)in_sizes; (void)n_in; (void)out_size;
    const float* x  = (const float*)d_in[0];
    const float* Wq = (const float*)d_in[1];
    const float* Wk = (const float*)d_in[2];
    const float* Wv = (const float*)d_in[3];
    float* out = (float*)d_out;

    qkv_kernel<<<dim3(DOUT / 128, (BATCH * NSEQ) / 128, 3), 256>>>(x, Wq, Wk, Wv);
    score_kernel<<<dim3(NSEQ / 128, NSEQ / 128, BATCH), 256>>>();
    softmax_kernel<<<BATCH * NSEQ, 256>>>();
    pv_kernel<<<dim3(DOUT / 128, NSEQ / 128, BATCH), 256>>>(out);
}

// round 3
// speedup vs baseline: 2.7869x; 2.7869x over previous
#include <cuda_runtime.h>
#include <cuda_bf16.h>
#include <cstdint>

#define NSEQ 2048
#define DIN  1024
#define DOUT 1024
#define BATCH 8

// ---------------- device scratch (no allocations allowed) ----------------
__device__ float g_Q[(size_t)BATCH * NSEQ * DOUT];
__device__ float g_K[(size_t)BATCH * NSEQ * DOUT];
__device__ float g_S[(size_t)BATCH * NSEQ * NSEQ];
__device__ __nv_bfloat16 g_Wt_hi[3ull * DOUT * DIN];   // W^T, K-major, split hi
__device__ __nv_bfloat16 g_Wt_lo[3ull * DOUT * DIN];
__device__ __nv_bfloat16 g_Vt_hi[(size_t)BATCH * DOUT * NSEQ]; // V^T per batch
__device__ __nv_bfloat16 g_Vt_lo[(size_t)BATCH * DOUT * NSEQ];

// ---------------- helpers ----------------
__device__ __forceinline__ uint32_t smem_u32(const void* p) {
    uint32_t a;
    asm("{ .reg .u64 t; cvta.to.shared.u64 t, %1; cvt.u32.u64 %0, t; }" : "=r"(a) : "l"(p));
    return a;
}

__device__ __forceinline__ void ldm_x4(uint32_t r[4], uint32_t addr) {
    asm volatile("ldmatrix.sync.aligned.m8n8.x4.shared.b16 {%0,%1,%2,%3}, [%4];"
                 : "=r"(r[0]), "=r"(r[1]), "=r"(r[2]), "=r"(r[3]) : "r"(addr));
}

__device__ __forceinline__ void mma16816(float* c, const uint32_t* a, const uint32_t* b) {
    asm volatile(
        "mma.sync.aligned.m16n8k16.row.col.f32.bf16.bf16.f32 "
        "{%0,%1,%2,%3}, {%4,%5,%6,%7}, {%8,%9}, {%0,%1,%2,%3};"
        : "+f"(c[0]), "+f"(c[1]), "+f"(c[2]), "+f"(c[3])
        : "r"(a[0]), "r"(a[1]), "r"(a[2]), "r"(a[3]), "r"(b[0]), "r"(b[1]));
}

__device__ __forceinline__ uint32_t pack2(__nv_bfloat16 a, __nv_bfloat16 b) {
    return (uint32_t)__bfloat16_as_ushort(a) | ((uint32_t)__bfloat16_as_ushort(b) << 16);
}
__device__ __forceinline__ void split2(float x, float y, uint32_t& hp, uint32_t& lp) {
    __nv_bfloat16 hx = __float2bfloat16_rn(x), hy = __float2bfloat16_rn(y);
    __nv_bfloat16 lx = __float2bfloat16_rn(x - __bfloat162float(hx));
    __nv_bfloat16 ly = __float2bfloat16_rn(y - __bfloat162float(hy));
    hp = pack2(hx, hy);
    lp = pack2(lx, ly);
}

// SMEM tile: 128 rows x 32 k, row stride 40 bf16 (80B) -> conflict-free ldmatrix
#define TSTRIDE 40

// ---------------- core mma.sync GEMM ----------------
// C[128,128] = A[fp32, K-major, lda] * B^T (B K-major).
// BMODE: 0 = B fp32 (split in-kernel), 1 = B pre-split bf16
// EMODE: 0 = fp32 C epilogue, 1 = split+transposed bf16 epilogue (V^T)
template <int BMODE, int EMODE>
__device__ __forceinline__ void gemm_mma(
    const float* __restrict__ A, int lda, int rowBase,
    const float* __restrict__ Bf,
    const __nv_bfloat16* __restrict__ BhiG, const __nv_bfloat16* __restrict__ BloG,
    int ldb, int colBase, int kEnd,
    float* __restrict__ C, int ldc,
    __nv_bfloat16* __restrict__ VtHi, __nv_bfloat16* __restrict__ VtLo)
{
    __shared__ __align__(16) __nv_bfloat16 sAhi[128 * TSTRIDE];
    __shared__ __align__(16) __nv_bfloat16 sAlo[128 * TSTRIDE];
    __shared__ __align__(16) __nv_bfloat16 sBhi[128 * TSTRIDE];
    __shared__ __align__(16) __nv_bfloat16 sBlo[128 * TSTRIDE];

    const int tid  = threadIdx.x;
    const int wid  = tid >> 5;
    const int lane = tid & 31;
    const int warpM = (wid >> 2) * 64;   // 2 warps in M
    const int warpN = (wid & 3) * 32;    // 4 warps in N

    const uint32_t aHiB = smem_u32(sAhi), aLoB = smem_u32(sAlo);
    const uint32_t bHiB = smem_u32(sBhi), bLoB = smem_u32(sBlo);

    // ldmatrix lane-address offsets (bytes)
    const uint32_t aOff = (uint32_t)(warpM + (lane & 15)) * 80 + ((lane >> 4) << 4);
    const uint32_t bOff = (uint32_t)(warpN + (lane & 7) + ((lane & 16) >> 1)) * 80 +
                          ((lane & 8) << 1);

    float acc[4][4][4];
#pragma unroll
    for (int i = 0; i < 4; i++)
#pragma unroll
        for (int j = 0; j < 4; j++)
#pragma unroll
            for (int e = 0; e < 4; e++) acc[i][j][e] = 0.0f;

    for (int k0 = 0; k0 < kEnd; k0 += 32) {
        // --- load A tile (fp32 -> hi/lo split) ---
#pragma unroll
        for (int i = 0; i < 4; i++) {
            int idx = tid + i * 256;          // 1024 float4 slots
            int row = idx >> 3;
            int c4  = (idx & 7) << 2;
            float4 v = *(const float4*)&A[(size_t)(rowBase + row) * lda + k0 + c4];
            uint32_t h0, h1, l0, l1;
            split2(v.x, v.y, h0, l0);
            split2(v.z, v.w, h1, l1);
            int off = row * TSTRIDE + c4;
            *(uint2*)&sAhi[off] = make_uint2(h0, h1);
            *(uint2*)&sAlo[off] = make_uint2(l0, l1);
        }
        // --- load B tile ---
        if (BMODE == 0) {
#pragma unroll
            for (int i = 0; i < 4; i++) {
                int idx = tid + i * 256;
                int row = idx >> 3;
                int c4  = (idx & 7) << 2;
                float4 v = *(const float4*)&Bf[(size_t)(colBase + row) * ldb + k0 + c4];
                uint32_t h0, h1, l0, l1;
                split2(v.x, v.y, h0, l0);
                split2(v.z, v.w, h1, l1);
                int off = row * TSTRIDE + c4;
                *(uint2*)&sBhi[off] = make_uint2(h0, h1);
                *(uint2*)&sBlo[off] = make_uint2(l0, l1);
            }
        } else {
#pragma unroll
            for (int i = 0; i < 2; i++) {
                int idx = tid + i * 256;      // 512 uint4 slots
                int row = idx >> 2;
                int c8  = (idx & 3) << 3;
                size_t g = (size_t)(colBase + row) * ldb + k0 + c8;
                int off = row * TSTRIDE + c8;
                *(uint4*)&sBhi[off] = *(const uint4*)&BhiG[g];
                *(uint4*)&sBlo[off] = *(const uint4*)&BloG[g];
            }
        }
        __syncthreads();

#pragma unroll
        for (int ks = 0; ks < 32; ks += 16) {
            uint32_t ah[4][4], al[4][4];
#pragma unroll
            for (int mi = 0; mi < 4; mi++) {
                uint32_t off = aOff + (uint32_t)mi * (16 * 80) + (uint32_t)ks * 2;
                ldm_x4(ah[mi], aHiB + off);
                ldm_x4(al[mi], aLoB + off);
            }
            uint32_t bh[4][2], bl[4][2];
#pragma unroll
            for (int n2 = 0; n2 < 2; n2++) {
                uint32_t off = bOff + (uint32_t)n2 * (16 * 80) + (uint32_t)ks * 2;
                uint32_t r[4];
                ldm_x4(r, bHiB + off);
                bh[n2 * 2][0] = r[0]; bh[n2 * 2][1] = r[1];
                bh[n2 * 2 + 1][0] = r[2]; bh[n2 * 2 + 1][1] = r[3];
                ldm_x4(r, bLoB + off);
                bl[n2 * 2][0] = r[0]; bl[n2 * 2][1] = r[1];
                bl[n2 * 2 + 1][0] = r[2]; bl[n2 * 2 + 1][1] = r[3];
            }
#pragma unroll
            for (int mi = 0; mi < 4; mi++)
#pragma unroll
                for (int ni = 0; ni < 4; ni++) {
                    mma16816(acc[mi][ni], ah[mi], bh[ni]);
                    mma16816(acc[mi][ni], ah[mi], bl[ni]);
                    mma16816(acc[mi][ni], al[mi], bh[ni]);
                }
        }
        __syncthreads();
    }

    // ---------------- epilogue ----------------
    const int mBase = warpM + (lane >> 2);
    const int nBase = warpN + (lane & 3) * 2;
    if (EMODE == 0) {
#pragma unroll
        for (int mi = 0; mi < 4; mi++)
#pragma unroll
            for (int ni = 0; ni < 4; ni++) {
                const float* c = acc[mi][ni];
                int r0 = rowBase + mBase + mi * 16;
                int cc = colBase + nBase + ni * 8;
                *(float2*)&C[(size_t)r0 * ldc + cc]       = make_float2(c[0], c[1]);
                *(float2*)&C[(size_t)(r0 + 8) * ldc + cc] = make_float2(c[2], c[3]);
            }
    } else {
        // V^T split write: element (seq=row, e=col) -> Vt[b][e][seq]
#pragma unroll
        for (int mi = 0; mi < 4; mi++)
#pragma unroll
            for (int ni = 0; ni < 4; ni++) {
                const float* c = acc[mi][ni];
#pragma unroll
                for (int e = 0; e < 4; e++) {
                    int row = rowBase + mBase + mi * 16 + (e >> 1) * 8;
                    int col = colBase + nBase + ni * 8 + (e & 1);
                    int b = row >> 11, nloc = row & (NSEQ - 1);
                    float x = c[e];
                    __nv_bfloat16 h = __float2bfloat16_rn(x);
                    __nv_bfloat16 l = __float2bfloat16_rn(x - __bfloat162float(h));
                    size_t o = ((size_t)b * DOUT + col) * NSEQ + nloc;
                    VtHi[o] = h;
                    VtLo[o] = l;
                }
            }
    }
}

// ---------------- kernels ----------------

// Transpose + bf16-split the three weight matrices: Wt[z][dout][din]
__global__ void __launch_bounds__(256) wsplit_kernel(
    const float* __restrict__ Wq, const float* __restrict__ Wk, const float* __restrict__ Wv)
{
    const int z = blockIdx.z;
    const float* W = (z == 0) ? Wq : (z == 1) ? Wk : Wv;
    __nv_bfloat16* H = g_Wt_hi + (size_t)z * DOUT * DIN;
    __nv_bfloat16* L = g_Wt_lo + (size_t)z * DOUT * DIN;

    __shared__ float t[32][33];
    const int j0 = blockIdx.x * 32;   // dout
    const int i0 = blockIdx.y * 32;   // din
    const int tx = threadIdx.x & 31, ty = threadIdx.x >> 5;
#pragma unroll
    for (int k = 0; k < 4; k++)
        t[ty + k * 8][tx] = W[(size_t)(i0 + ty + k * 8) * DOUT + j0 + tx];
    __syncthreads();
#pragma unroll
    for (int k = 0; k < 4; k++) {
        float x = t[tx][ty + k * 8];
        __nv_bfloat16 h = __float2bfloat16_rn(x);
        __nv_bfloat16 l = __float2bfloat16_rn(x - __bfloat162float(h));
        size_t o = (size_t)(j0 + ty + k * 8) * DIN + i0 + tx;
        H[o] = h;
        L[o] = l;
    }
}

// QKV projections. z=0 -> Q (fp32), z=1 -> K (fp32), z=2 -> V (transposed bf16 split)
__global__ void __launch_bounds__(256, 2) qkv_kernel(const float* __restrict__ X)
{
    const int z = blockIdx.z;
    const __nv_bfloat16* bh = g_Wt_hi + (size_t)z * DOUT * DIN;
    const __nv_bfloat16* bl = g_Wt_lo + (size_t)z * DOUT * DIN;
    const int rowBase = blockIdx.y * 128;
    const int colBase = blockIdx.x * 128;
    if (z == 2)
        gemm_mma<1, 1>(X, DIN, rowBase, nullptr, bh, bl, DIN, colBase, DIN,
                       nullptr, 0, g_Vt_hi, g_Vt_lo);
    else
        gemm_mma<1, 0>(X, DIN, rowBase, nullptr, bh, bl, DIN, colBase, DIN,
                       (z == 0) ? g_Q : g_K, DOUT, nullptr, nullptr);
}

// Scores S = Q K^T (causal tile skip)
__global__ void __launch_bounds__(256, 2) score_kernel()
{
    const int b = blockIdx.z, qT = blockIdx.y, kT = blockIdx.x;
    if (kT > qT) return;
    const float* Qb = g_Q + (size_t)b * NSEQ * DOUT;
    const float* Kb = g_K + (size_t)b * NSEQ * DOUT;
    float*       Sb = g_S + (size_t)b * NSEQ * NSEQ;
    gemm_mma<0, 0>(Qb, DOUT, qT * 128, Kb, nullptr, nullptr, DOUT, kT * 128, DOUT,
                   Sb, NSEQ, nullptr, nullptr);
}

// Causal softmax (scale 1/32), zero-fills masked entries to the 128 boundary.
__global__ void __launch_bounds__(256) softmax_kernel()
{
    const int row = blockIdx.x;
    const int b = row >> 11;
    const int q = row & (NSEQ - 1);
    float* s = g_S + (size_t)b * NSEQ * NSEQ + (size_t)q * NSEQ;

    const int len = q + 1;
    const int alignedLen = (len + 127) & ~127;

    float v[8];
    float m = -1e30f;
#pragma unroll
    for (int i = 0; i < 8; i++) {
        int idx = threadIdx.x + i * 256;
        v[i] = (idx < len) ? s[idx] * 0.03125f : -1e30f;
        m = fmaxf(m, v[i]);
    }
    __shared__ float red[256];
    red[threadIdx.x] = m;
    __syncthreads();
#pragma unroll
    for (int off = 128; off > 0; off >>= 1) {
        if (threadIdx.x < off)
            red[threadIdx.x] = fmaxf(red[threadIdx.x], red[threadIdx.x + off]);
        __syncthreads();
    }
    m = red[0];
    __syncthreads();
    float sum = 0.0f;
#pragma unroll
    for (int i = 0; i < 8; i++) {
        float e = __expf(v[i] - m);
        v[i] = e;
        sum += e;
    }
    red[threadIdx.x] = sum;
    __syncthreads();
#pragma unroll
    for (int off = 128; off > 0; off >>= 1) {
        if (threadIdx.x < off)
            red[threadIdx.x] += red[threadIdx.x + off];
        __syncthreads();
    }
    const float inv = 1.0f / red[0];
#pragma unroll
    for (int i = 0; i < 8; i++) {
        int idx = threadIdx.x + i * 256;
        if (idx < alignedLen)
            s[idx] = (idx < len) ? v[i] * inv : 0.0f;
    }
}

// context = P V (P fp32 split in-kernel, V^T pre-split bf16), causal K extent.
__global__ void __launch_bounds__(256, 2) pv_kernel(float* __restrict__ out)
{
    const int b = blockIdx.z, qT = blockIdx.y;
    const float* Sb = g_S + (size_t)b * NSEQ * NSEQ;
    const __nv_bfloat16* vh = g_Vt_hi + (size_t)b * DOUT * NSEQ;
    const __nv_bfloat16* vl = g_Vt_lo + (size_t)b * DOUT * NSEQ;
    float* Ob = out + (size_t)b * NSEQ * DOUT;
    gemm_mma<1, 0>(Sb, NSEQ, qT * 128, nullptr, vh, vl, NSEQ, blockIdx.x * 128,
                   (qT + 1) * 128, Ob, DOUT, nullptr, nullptr);
}

// ---------------- launch ----------------
extern "C" void kernel_launch(void* const* d_in, const int* in_sizes, int n_in,
                              void* d_out, int out_size)
{
    (void)in_sizes; (void)n_in; (void)out_size;
    const float* x  = (const float*)d_in[0];
    const float* Wq = (const float*)d_in[1];
    const float* Wk = (const float*)d_in[2];
    const float* Wv = (const float*)d_in[3];
    float* out = (float*)d_out;

    wsplit_kernel<<<dim3(32, 32, 3), 256>>>(Wq, Wk, Wv);
    qkv_kernel<<<dim3(DOUT / 128, (BATCH * NSEQ) / 128, 3), 256>>>(x);
    score_kernel<<<dim3(NSEQ / 128, NSEQ / 128, BATCH), 256>>>();
    softmax_kernel<<<BATCH * NSEQ, 256>>>();
    pv_kernel<<<dim3(DOUT / 128, NSEQ / 128, BATCH), 256>>>(out);
}

// round 4
// speedup vs baseline: 2.8718x; 1.0305x over previous
#include <cuda_runtime.h>
#include <cuda_bf16.h>
#include <cstdint>

#define NSEQ 2048
#define DIN  1024
#define DOUT 1024
#define BATCH 8
#define NTOK  (BATCH * NSEQ)   // 16384

// ---------------- device scratch (no allocations allowed) ----------------
__device__ float g_S[(size_t)BATCH * NSEQ * NSEQ];
__device__ __nv_bfloat16 g_Xhi[(size_t)NTOK * DIN];
__device__ __nv_bfloat16 g_Xlo[(size_t)NTOK * DIN];
__device__ __nv_bfloat16 g_Wt_hi[3ull * DOUT * DIN];
__device__ __nv_bfloat16 g_Wt_lo[3ull * DOUT * DIN];
__device__ __nv_bfloat16 g_Qhi[(size_t)NTOK * DOUT];
__device__ __nv_bfloat16 g_Qlo[(size_t)NTOK * DOUT];
__device__ __nv_bfloat16 g_Khi[(size_t)NTOK * DOUT];
__device__ __nv_bfloat16 g_Klo[(size_t)NTOK * DOUT];
__device__ __nv_bfloat16 g_Vt_hi[(size_t)BATCH * DOUT * NSEQ];
__device__ __nv_bfloat16 g_Vt_lo[(size_t)BATCH * DOUT * NSEQ];
__device__ __nv_bfloat16 g_Phi[(size_t)BATCH * NSEQ * NSEQ];
__device__ __nv_bfloat16 g_Plo[(size_t)BATCH * NSEQ * NSEQ];

// ---------------- helpers ----------------
__device__ __forceinline__ uint32_t smem_u32(const void* p) {
    uint32_t a;
    asm("{ .reg .u64 t; cvta.to.shared.u64 t, %1; cvt.u32.u64 %0, t; }" : "=r"(a) : "l"(p));
    return a;
}
__device__ __forceinline__ void ldm_x4(uint32_t r[4], uint32_t addr) {
    asm volatile("ldmatrix.sync.aligned.m8n8.x4.shared.b16 {%0,%1,%2,%3}, [%4];"
                 : "=r"(r[0]), "=r"(r[1]), "=r"(r[2]), "=r"(r[3]) : "r"(addr));
}
__device__ __forceinline__ void mma16816(float* c, const uint32_t* a, const uint32_t* b) {
    asm volatile(
        "mma.sync.aligned.m16n8k16.row.col.f32.bf16.bf16.f32 "
        "{%0,%1,%2,%3}, {%4,%5,%6,%7}, {%8,%9}, {%0,%1,%2,%3};"
        : "+f"(c[0]), "+f"(c[1]), "+f"(c[2]), "+f"(c[3])
        : "r"(a[0]), "r"(a[1]), "r"(a[2]), "r"(a[3]), "r"(b[0]), "r"(b[1]));
}
#define CP16(dst, src) \
    asm volatile("cp.async.cg.shared.global [%0], [%1], 16;" :: "r"(dst), "l"(src))
#define CPCOMMIT() asm volatile("cp.async.commit_group;" ::: "memory")
#define CPWAIT1()  asm volatile("cp.async.wait_group 1;" ::: "memory")
#define CPWAIT0()  asm volatile("cp.async.wait_group 0;" ::: "memory")

__device__ __forceinline__ uint32_t pack2(__nv_bfloat16 a, __nv_bfloat16 b) {
    return (uint32_t)__bfloat16_as_ushort(a) | ((uint32_t)__bfloat16_as_ushort(b) << 16);
}
__device__ __forceinline__ void split2(float x, float y, uint32_t& hp, uint32_t& lp) {
    __nv_bfloat16 hx = __float2bfloat16_rn(x), hy = __float2bfloat16_rn(y);
    __nv_bfloat16 lx = __float2bfloat16_rn(x - __bfloat162float(hx));
    __nv_bfloat16 ly = __float2bfloat16_rn(y - __bfloat162float(hy));
    hp = pack2(hx, hy);
    lp = pack2(lx, ly);
}

// SMEM tile: 128 rows x 32 k bf16, 80B row stride (conflict-free ldmatrix).
#define TBYTES   10240            // one tile
#define STG      40960            // 4 tiles per stage
#define SMEM_SZ  (2 * STG)        // 81920 B

// issue cp.async for one hi/lo tile pair (128x32) into stage SMEM
__device__ __forceinline__ void stage_load(
    uint32_t sHi, const __nv_bfloat16* __restrict__ hi,
    const __nv_bfloat16* __restrict__ lo, int ld, int base, int k0, int tid)
{
#pragma unroll
    for (int i = 0; i < 2; i++) {
        int idx = tid + i * 256;           // 512 chunks per tile
        int row = idx >> 2;
        int c   = idx & 3;                 // 16B chunk within row
        size_t g = (size_t)(base + row) * ld + k0 + c * 8;
        uint32_t d = sHi + row * 80 + c * 16;
        CP16(d, hi + g);
        CP16(d + TBYTES, lo + g);
    }
}

// ---------------- core GEMM: all operands pre-split bf16 ----------------
// EMODE: 0 = fp32 C, 1 = split+transposed V^T, 2 = split row-major (Q/K)
template <int EMODE>
__device__ __forceinline__ void gemm_ps(
    const __nv_bfloat16* __restrict__ AhiG, const __nv_bfloat16* __restrict__ AloG,
    int lda, int aBase,
    const __nv_bfloat16* __restrict__ BhiG, const __nv_bfloat16* __restrict__ BloG,
    int ldb, int bBase, int kEnd,
    float* __restrict__ C, int ldOut, int oRow, int oCol,
    __nv_bfloat16* __restrict__ OHi, __nv_bfloat16* __restrict__ OLo)
{
    extern __shared__ char smem[];
    const int tid  = threadIdx.x;
    const int wid  = tid >> 5;
    const int lane = tid & 31;
    const int warpM = (wid >> 2) * 64;
    const int warpN = (wid & 3) * 32;

    const uint32_t sb = smem_u32(smem);
    const uint32_t stB[2] = { sb, sb + STG };

    const uint32_t aOff = (uint32_t)(warpM + (lane & 15)) * 80 + ((lane >> 4) << 4);
    const uint32_t bOff = (uint32_t)(warpN + (lane & 7) + ((lane & 16) >> 1)) * 80 +
                          ((lane & 8) << 1);

    float acc[4][4][4];
#pragma unroll
    for (int i = 0; i < 4; i++)
#pragma unroll
        for (int j = 0; j < 4; j++)
#pragma unroll
            for (int e = 0; e < 4; e++) acc[i][j][e] = 0.0f;

    // prologue: chunk 0 -> stage 0
    stage_load(stB[0],         AhiG, AloG, lda, aBase, 0, tid);
    stage_load(stB[0] + 20480, BhiG, BloG, ldb, bBase, 0, tid);
    CPCOMMIT();

    const int NC = kEnd >> 5;
    for (int c = 0; c < NC; c++) {
        const int st = c & 1;
        if (c + 1 < NC) {
            const int k0 = (c + 1) << 5;
            stage_load(stB[st ^ 1],         AhiG, AloG, lda, aBase, k0, tid);
            stage_load(stB[st ^ 1] + 20480, BhiG, BloG, ldb, bBase, k0, tid);
            CPCOMMIT();
            CPWAIT1();
        } else {
            CPWAIT0();
        }
        __syncthreads();

        const uint32_t aHiB = stB[st],          aLoB = stB[st] + TBYTES;
        const uint32_t bHiB = stB[st] + 20480,  bLoB = stB[st] + 30720;
#pragma unroll
        for (int ks = 0; ks < 2; ks++) {
            const uint32_t ko = (uint32_t)ks * 32;    // 16 bf16 = 32 bytes
            uint32_t ah[4][4], al[4][4];
#pragma unroll
            for (int mi = 0; mi < 4; mi++) {
                uint32_t off = aOff + (uint32_t)mi * (16 * 80) + ko;
                ldm_x4(ah[mi], aHiB + off);
                ldm_x4(al[mi], aLoB + off);
            }
            uint32_t bh[4][2], bl[4][2];
#pragma unroll
            for (int n2 = 0; n2 < 2; n2++) {
                uint32_t off = bOff + (uint32_t)n2 * (16 * 80) + ko;
                uint32_t r[4];
                ldm_x4(r, bHiB + off);
                bh[n2 * 2][0] = r[0]; bh[n2 * 2][1] = r[1];
                bh[n2 * 2 + 1][0] = r[2]; bh[n2 * 2 + 1][1] = r[3];
                ldm_x4(r, bLoB + off);
                bl[n2 * 2][0] = r[0]; bl[n2 * 2][1] = r[1];
                bl[n2 * 2 + 1][0] = r[2]; bl[n2 * 2 + 1][1] = r[3];
            }
#pragma unroll
            for (int mi = 0; mi < 4; mi++)
#pragma unroll
                for (int ni = 0; ni < 4; ni++) {
                    mma16816(acc[mi][ni], ah[mi], bh[ni]);
                    mma16816(acc[mi][ni], ah[mi], bl[ni]);
                    mma16816(acc[mi][ni], al[mi], bh[ni]);
                }
        }
        __syncthreads();
    }

    // ---------------- epilogue ----------------
    const int mBase = warpM + (lane >> 2);
    const int nBase = warpN + (lane & 3) * 2;
    if (EMODE == 0) {
#pragma unroll
        for (int mi = 0; mi < 4; mi++)
#pragma unroll
            for (int ni = 0; ni < 4; ni++) {
                const float* c = acc[mi][ni];
                int r0 = oRow + mBase + mi * 16;
                int cc = oCol + nBase + ni * 8;
                *(float2*)&C[(size_t)r0 * ldOut + cc]       = make_float2(c[0], c[1]);
                *(float2*)&C[(size_t)(r0 + 8) * ldOut + cc] = make_float2(c[2], c[3]);
            }
    } else if (EMODE == 2) {
#pragma unroll
        for (int mi = 0; mi < 4; mi++)
#pragma unroll
            for (int ni = 0; ni < 4; ni++) {
                const float* c = acc[mi][ni];
#pragma unroll
                for (int h = 0; h < 2; h++) {        // row halves (+0, +8)
                    int r0 = oRow + mBase + mi * 16 + h * 8;
                    int cc = oCol + nBase + ni * 8;
                    uint32_t hp, lp;
                    split2(c[h * 2], c[h * 2 + 1], hp, lp);
                    *(uint32_t*)&OHi[(size_t)r0 * ldOut + cc] = hp;
                    *(uint32_t*)&OLo[(size_t)r0 * ldOut + cc] = lp;
                }
            }
    } else {
        // V^T split write: (seq=row, e=col) -> Vt[b][e][seq]
#pragma unroll
        for (int mi = 0; mi < 4; mi++)
#pragma unroll
            for (int ni = 0; ni < 4; ni++) {
                const float* c = acc[mi][ni];
#pragma unroll
                for (int e = 0; e < 4; e++) {
                    int row = oRow + mBase + mi * 16 + (e >> 1) * 8;
                    int col = oCol + nBase + ni * 8 + (e & 1);
                    int b = row >> 11, nloc = row & (NSEQ - 1);
                    float x = c[e];
                    __nv_bfloat16 h = __float2bfloat16_rn(x);
                    __nv_bfloat16 l = __float2bfloat16_rn(x - __bfloat162float(h));
                    size_t o = ((size_t)b * DOUT + col) * NSEQ + nloc;
                    OHi[o] = h;
                    OLo[o] = l;
                }
            }
    }
}

// ---------------- kernels ----------------

// Split x into bf16 hi/lo. 16M elems, 4 per thread.
__global__ void __launch_bounds__(256) xsplit_kernel(const float* __restrict__ X)
{
    size_t i4 = (size_t)blockIdx.x * 256 + threadIdx.x;   // float4 index
    float4 v = *(const float4*)&X[i4 * 4];
    uint32_t h0, h1, l0, l1;
    split2(v.x, v.y, h0, l0);
    split2(v.z, v.w, h1, l1);
    *(uint2*)&g_Xhi[i4 * 4] = make_uint2(h0, h1);
    *(uint2*)&g_Xlo[i4 * 4] = make_uint2(l0, l1);
}

// Transpose + split weights: Wt[z][dout][din]
__global__ void __launch_bounds__(256) wsplit_kernel(
    const float* __restrict__ Wq, const float* __restrict__ Wk, const float* __restrict__ Wv)
{
    const int z = blockIdx.z;
    const float* W = (z == 0) ? Wq : (z == 1) ? Wk : Wv;
    __nv_bfloat16* H = g_Wt_hi + (size_t)z * DOUT * DIN;
    __nv_bfloat16* L = g_Wt_lo + (size_t)z * DOUT * DIN;

    __shared__ float t[32][33];
    const int j0 = blockIdx.x * 32;
    const int i0 = blockIdx.y * 32;
    const int tx = threadIdx.x & 31, ty = threadIdx.x >> 5;
#pragma unroll
    for (int k = 0; k < 4; k++)
        t[ty + k * 8][tx] = W[(size_t)(i0 + ty + k * 8) * DOUT + j0 + tx];
    __syncthreads();
#pragma unroll
    for (int k = 0; k < 4; k++) {
        float x = t[tx][ty + k * 8];
        __nv_bfloat16 h = __float2bfloat16_rn(x);
        __nv_bfloat16 l = __float2bfloat16_rn(x - __bfloat162float(h));
        size_t o = (size_t)(j0 + ty + k * 8) * DIN + i0 + tx;
        H[o] = h;
        L[o] = l;
    }
}

// QKV: z=0 -> Q split, z=1 -> K split, z=2 -> V^T split
__global__ void __launch_bounds__(256, 2) qkv_kernel()
{
    const int z = blockIdx.z;
    const __nv_bfloat16* bh = g_Wt_hi + (size_t)z * DOUT * DIN;
    const __nv_bfloat16* bl = g_Wt_lo + (size_t)z * DOUT * DIN;
    const int rowBase = blockIdx.y * 128;
    const int colBase = blockIdx.x * 128;
    if (z == 2)
        gemm_ps<1>(g_Xhi, g_Xlo, DIN, rowBase, bh, bl, DIN, colBase, DIN,
                   nullptr, 0, rowBase, colBase, g_Vt_hi, g_Vt_lo);
    else if (z == 0)
        gemm_ps<2>(g_Xhi, g_Xlo, DIN, rowBase, bh, bl, DIN, colBase, DIN,
                   nullptr, DOUT, rowBase, colBase, g_Qhi, g_Qlo);
    else
        gemm_ps<2>(g_Xhi, g_Xlo, DIN, rowBase, bh, bl, DIN, colBase, DIN,
                   nullptr, DOUT, rowBase, colBase, g_Khi, g_Klo);
}

// Scores S = Q K^T (causal tile skip)
__global__ void __launch_bounds__(256, 2) score_kernel()
{
    const int b = blockIdx.z, qT = blockIdx.y, kT = blockIdx.x;
    if (kT > qT) return;
    gemm_ps<0>(g_Qhi, g_Qlo, DOUT, b * NSEQ + qT * 128,
               g_Khi, g_Klo, DOUT, b * NSEQ + kT * 128, DOUT,
               g_S + (size_t)b * NSEQ * NSEQ, NSEQ, qT * 128, kT * 128,
               nullptr, nullptr);
}

// Causal softmax; writes pre-split bf16 P with automatic zero-fill.
__global__ void __launch_bounds__(256) softmax_kernel()
{
    const int row = blockIdx.x;
    const int b = row >> 11;
    const int q = row & (NSEQ - 1);
    const size_t rb = (size_t)b * NSEQ * NSEQ + (size_t)q * NSEQ;
    const float* s = g_S + rb;

    const int len = q + 1;
    const int alignedLen = (len + 127) & ~127;

    float v[8];
    float m = -1e30f;
#pragma unroll
    for (int i = 0; i < 2; i++) {
        int base = (threadIdx.x + i * 256) * 4;
        if (base < alignedLen) {
            float4 x = *(const float4*)&s[base];
            v[i * 4 + 0] = (base + 0 < len) ? x.x * 0.03125f : -1e30f;
            v[i * 4 + 1] = (base + 1 < len) ? x.y * 0.03125f : -1e30f;
            v[i * 4 + 2] = (base + 2 < len) ? x.z * 0.03125f : -1e30f;
            v[i * 4 + 3] = (base + 3 < len) ? x.w * 0.03125f : -1e30f;
        } else {
            v[i * 4] = v[i * 4 + 1] = v[i * 4 + 2] = v[i * 4 + 3] = -1e30f;
        }
#pragma unroll
        for (int e = 0; e < 4; e++) m = fmaxf(m, v[i * 4 + e]);
    }

    __shared__ float red[256];
    red[threadIdx.x] = m;
    __syncthreads();
#pragma unroll
    for (int off = 128; off > 0; off >>= 1) {
        if (threadIdx.x < off)
            red[threadIdx.x] = fmaxf(red[threadIdx.x], red[threadIdx.x + off]);
        __syncthreads();
    }
    m = red[0];
    __syncthreads();

    float sum = 0.0f;
#pragma unroll
    for (int i = 0; i < 8; i++) {
        float e = __expf(v[i] - m);   // masked lanes -> 0
        v[i] = e;
        sum += e;
    }
    red[threadIdx.x] = sum;
    __syncthreads();
#pragma unroll
    for (int off = 128; off > 0; off >>= 1) {
        if (threadIdx.x < off)
            red[threadIdx.x] += red[threadIdx.x + off];
        __syncthreads();
    }
    const float inv = 1.0f / red[0];

#pragma unroll
    for (int i = 0; i < 2; i++) {
        int base = (threadIdx.x + i * 256) * 4;
        if (base < alignedLen) {
            float p0 = v[i * 4] * inv, p1 = v[i * 4 + 1] * inv;
            float p2 = v[i * 4 + 2] * inv, p3 = v[i * 4 + 3] * inv;
            uint32_t h0, h1, l0, l1;
            split2(p0, p1, h0, l0);
            split2(p2, p3, h1, l1);
            *(uint2*)&g_Phi[rb + base] = make_uint2(h0, h1);
            *(uint2*)&g_Plo[rb + base] = make_uint2(l0, l1);
        }
    }
}

// context = P V, causal K extent.
__global__ void __launch_bounds__(256, 2) pv_kernel(float* __restrict__ out)
{
    const int b = blockIdx.z, qT = blockIdx.y;
    gemm_ps<0>(g_Phi, g_Plo, NSEQ, b * NSEQ + qT * 128,
               g_Vt_hi, g_Vt_lo, NSEQ, b * DOUT + blockIdx.x * 128,
               (qT + 1) * 128,
               out + (size_t)b * NSEQ * DOUT, DOUT, qT * 128, blockIdx.x * 128,
               nullptr, nullptr);
}

// ---------------- launch ----------------
extern "C" void kernel_launch(void* const* d_in, const int* in_sizes, int n_in,
                              void* d_out, int out_size)
{
    (void)in_sizes; (void)n_in; (void)out_size;
    const float* x  = (const float*)d_in[0];
    const float* Wq = (const float*)d_in[1];
    const float* Wk = (const float*)d_in[2];
    const float* Wv = (const float*)d_in[3];
    float* out = (float*)d_out;

    cudaFuncSetAttribute(qkv_kernel,   cudaFuncAttributeMaxDynamicSharedMemorySize, SMEM_SZ);
    cudaFuncSetAttribute(score_kernel, cudaFuncAttributeMaxDynamicSharedMemorySize, SMEM_SZ);
    cudaFuncSetAttribute(pv_kernel,    cudaFuncAttributeMaxDynamicSharedMemorySize, SMEM_SZ);

    xsplit_kernel<<<NTOK * DIN / 1024, 256>>>(x);
    wsplit_kernel<<<dim3(32, 32, 3), 256>>>(Wq, Wk, Wv);
    qkv_kernel<<<dim3(DOUT / 128, NTOK / 128, 3), 256, SMEM_SZ>>>();
    score_kernel<<<dim3(NSEQ / 128, NSEQ / 128, BATCH), 256, SMEM_SZ>>>();
    softmax_kernel<<<BATCH * NSEQ, 256>>>();
    pv_kernel<<<dim3(DOUT / 128, NSEQ / 128, BATCH), 256, SMEM_SZ>>>(out);
}